// round 16
// baseline (speedup 1.0000x reference)
#include <cuda_runtime.h>
#include <cstdint>
#include <math.h>

// ---------------- problem constants ----------------
#define MROWS   65536        // B*N
#define FDIM    128
#define KCLUST  512
#define TM      64           // rows per CTA
#define TKC     32           // clusters per chunk
#define NCHUNK  (KCLUST / TKC)   // 16
#define THREADS 256

// ---------------- SMEM layout (float offsets) ----------------
// UNION region: XF staging (prologue only) overlays B1/B2/PF (main loop).
// XF : X (tf32-prerounded) in A-frag order. rows = mt(4)*16+ks(16), pitch 132 (8448 f)
// B1H: C chunk tf32, GEMM1 B-frag order (n=cluster,k=feat). rows=nt(4)*16+ks(16), pitch 66
// B2H: C chunk tf32, GEMM2 B-frag order (n=feat,k=cluster). rows=ks2(4)*16+nt2(16), pitch 66
// PF : P chunk (tf32-prerounded), GEMM2 A-frag order. rows = wm(4)*4+ksp(4), pitch 132
#define XF_OFF   0
#define B1H_OFF  0
#define B1_SZ    (64 * 66)
#define B2H_OFF  (B1H_OFF + B1_SZ)
#define B2_SZ    (64 * 66)
#define PF_OFF   (B2H_OFF + B2_SZ)
#define PF_SZ    (16 * 132)
#define UNION_SZ (B1_SZ + B2_SZ + PF_SZ)     // 10560 > XF 8448
#define CSQ_OFF  UNION_SZ
#define XSQ_OFF  (CSQ_OFF + 512)
#define ZS_OFF   (XSQ_OFF + 64)
#define SMEM_FLOATS (ZS_OFF + 64)
#define SMEM_BYTES  (SMEM_FLOATS * 4)

__device__ float g_csq[KCLUST];

__device__ __forceinline__ uint32_t f2tf32(float x) {
    uint32_t h; asm("cvt.rna.tf32.f32 %0, %1;" : "=r"(h) : "f"(x)); return h;
}

// D(16x8) += A(16x8,tf32) * B(8x8,tf32), fp32 accumulate
__device__ __forceinline__ void mma8(float* d, const uint32_t* a, float2 b) {
    asm volatile(
        "mma.sync.aligned.m16n8k8.row.col.f32.tf32.tf32.f32 "
        "{%0,%1,%2,%3}, {%4,%5,%6,%7}, {%8,%9}, {%0,%1,%2,%3};"
        : "+f"(d[0]), "+f"(d[1]), "+f"(d[2]), "+f"(d[3])
        : "r"(a[0]), "r"(a[1]), "r"(a[2]), "r"(a[3]),
          "r"(__float_as_uint(b.x)), "r"(__float_as_uint(b.y)));
}

__global__ void csq_kernel(const float* __restrict__ cc) {
    int c = blockIdx.x * blockDim.x + threadIdx.x;
    if (c < KCLUST) {
        const float* p = cc + (size_t)c * FDIM;
        float s = 0.f;
        #pragma unroll 16
        for (int f = 0; f < FDIM; ++f) s = fmaf(p[f], p[f], s);
        g_csq[c] = s;
    }
}

extern __shared__ float sm[];

__global__ __launch_bounds__(THREADS, 2)
void cluster_mma_kernel(const float* __restrict__ x, const float* __restrict__ cc,
                        float* __restrict__ out) {
    const int tid  = threadIdx.x;
    const int wid  = tid >> 5;      // 0..7
    const int lane = tid & 31;
    const int g    = lane >> 2;     // groupID (row within m16 tile)
    const int tig  = tid & 3;       // thread-in-group (== lane & 3)
    const int wm   = wid & 3;       // warp m-group: owns m-tile wm (rows wm*16..+16)
    const int wn   = wid >> 2;      // warp n-group: 0..1

    // ------- prologue: stage pre-rounded tf32 X (A-frag order) + exact row sumsq -------
    const float* xbase = x + (size_t)blockIdx.x * TM * FDIM;
    #pragma unroll
    for (int q = 0; q < 8; ++q) {
        int row = q * 8 + wid;                 // 0..63
        float4 v = *(const float4*)(xbase + row * FDIM + lane * 4);
        float s = v.x * v.x + v.y * v.y + v.z * v.z + v.w * v.w;
        #pragma unroll
        for (int m = 16; m; m >>= 1) s += __shfl_xor_sync(0xffffffffu, s, m);
        if (lane == 0) sm[XSQ_OFF + row] = s;
        int mt = row >> 4, rm = row & 15;
        int ks = lane >> 1;
        int base = (mt * 16 + ks) * 132 + (rm & 7) * 16 + (rm >> 3) + 2 * (lane & 1);
        #pragma unroll
        for (int j = 0; j < 4; ++j)
            sm[XF_OFF + base + j * 4] = __uint_as_float(f2tf32((&v.x)[j]));
    }
    sm[CSQ_OFF + tid]       = g_csq[tid];
    sm[CSQ_OFF + 256 + tid] = g_csq[256 + tid];
    if (tid < 64) sm[ZS_OFF + tid] = 0.f;
    __syncthreads();

    // ---- hoist this warp's A fragments (chunk-invariant) into registers ----
    uint32_t afrag[16][4];
    #pragma unroll
    for (int ks = 0; ks < 16; ++ks) {
        float4 av = *(const float4*)(sm + XF_OFF + (wm * 16 + ks) * 132 + lane * 4);
        afrag[ks][0] = __float_as_uint(av.x);
        afrag[ks][1] = __float_as_uint(av.y);
        afrag[ks][2] = __float_as_uint(av.z);
        afrag[ks][3] = __float_as_uint(av.w);
    }
    float xs[2];
    #pragma unroll
    for (int b = 0; b < 2; ++b)
        xs[b] = sm[XSQ_OFF + wm * 16 + g + 8 * b];

    float d2acc[8][4];
    #pragma unroll
    for (int nt = 0; nt < 8; ++nt)
        #pragma unroll
        for (int i = 0; i < 4; ++i) d2acc[nt][i] = 0.f;
    float zacc[2] = {0.f, 0.f};

    // prefetch chunk 0 of C into registers (32 clusters x 128 feats)
    float4 pre[4];
    #pragma unroll
    for (int q = 0; q < 4; ++q) {
        int cl = q * 8 + wid;
        pre[q] = *(const float4*)(cc + (size_t)cl * FDIM + lane * 4);
    }

    for (int kc = 0; kc < NCHUNK; ++kc) {
        __syncthreads();   // prev chunk's consumers done; (kc=0: a-frag reads done)

        // ---- stage C chunk from prefetch regs: B1H (k=feat) + B2H (k=cluster) ----
        #pragma unroll
        for (int q = 0; q < 4; ++q) {
            int cl = q * 8 + wid;                      // warp-uniform cluster 0..31
            int nt = cl >> 3;                          // 0..3
            int ks = lane >> 1;
            int a1base = (nt * 16 + ks) * 66 + (cl & 7) * 8 + (lane & 1);
            int a2base = (nt * 16 + ks) * 66 + (lane & 1) * 32 + (cl & 3) * 2 + ((cl & 7) >> 2);
            #pragma unroll
            for (int j = 0; j < 4; ++j) {
                float hi = __uint_as_float(f2tf32((&pre[q].x)[j]));
                sm[B1H_OFF + a1base + j * 2] = hi;
                sm[B2H_OFF + a2base + j * 8] = hi;
            }
        }
        __syncthreads();

        // prefetch next chunk (latency hidden behind GEMM1 + epilogue)
        if (kc + 1 < NCHUNK) {
            #pragma unroll
            for (int q = 0; q < 4; ++q) {
                int cl = (kc + 1) * TKC + q * 8 + wid;
                pre[q] = *(const float4*)(cc + (size_t)cl * FDIM + lane * 4);
            }
        }

        // ---- GEMM1: S = x . C^T  (A from registers, zero A-LDS) ----
        float sacc[2][4];
        #pragma unroll
        for (int nt = 0; nt < 2; ++nt)
            #pragma unroll
            for (int i = 0; i < 4; ++i) sacc[nt][i] = 0.f;

        #pragma unroll
        for (int ks = 0; ks < 16; ++ks) {
            #pragma unroll
            for (int nt = 0; nt < 2; ++nt) {
                int ntg = wn * 2 + nt;
                float2 bh = *(const float2*)(sm + B1H_OFF + (ntg * 16 + ks) * 66 + lane * 2);
                mma8(sacc[nt], afrag[ks], bh);
            }
        }

        // ---- epilogue: p = exp(-sqrt(xsq+csq-2s)); consistent rna rounding ----
        #pragma unroll
        for (int nt = 0; nt < 2; ++nt) {
            int ksp = wn * 2 + nt;
            #pragma unroll
            for (int i = 0; i < 4; ++i) {
                int b   = i >> 1;                 // row-high
                int clo = 2 * tig + (i & 1);      // cluster within 8-tile
                int clg = kc * TKC + ksp * 8 + clo;
                float s   = sacc[nt][i];
                float d2v = fmaf(-2.f, s, xs[b] + sm[CSQ_OFF + clg]);
                float d   = sqrtf(fmaxf(d2v, 0.f));
                float p   = __expf(-d);
                float pr  = __uint_as_float(f2tf32(p));   // rna-rounded
                zacc[b] += pr;
                sm[PF_OFF + (wm * 4 + ksp) * 132 +
                   (g * 4 + (clo & 3)) * 4 + b + 2 * (clo >> 2)] = pr;
            }
        }
        // PF rows of this wm-group produced/consumed only by its 2 warps
        asm volatile("bar.sync %0, 64;" :: "r"(1 + wm) : "memory");

        // ---- GEMM2: D2 += P . C_chunk  (A pre-rounded, no cvt) ----
        #pragma unroll
        for (int ks2 = 0; ks2 < 4; ++ks2) {
            uint32_t pa[4];
            float4 pv = *(const float4*)(sm + PF_OFF + (wm * 4 + ks2) * 132 + lane * 4);
            pa[0] = __float_as_uint(pv.x);
            pa[1] = __float_as_uint(pv.y);
            pa[2] = __float_as_uint(pv.z);
            pa[3] = __float_as_uint(pv.w);
            #pragma unroll
            for (int nt2 = 0; nt2 < 8; ++nt2) {
                int n2g = wn * 8 + nt2;
                float2 b = *(const float2*)(sm + B2H_OFF + (ks2 * 16 + n2g) * 66 + lane * 2);
                mma8(d2acc[nt2], pa, b);
            }
        }
    }

    // ---- Z reduction across tig lanes + the two wn warp-groups ----
    #pragma unroll
    for (int b = 0; b < 2; ++b) {
        float z = zacc[b];
        z += __shfl_xor_sync(0xffffffffu, z, 1);
        z += __shfl_xor_sync(0xffffffffu, z, 2);
        if (tig == 0)
            atomicAdd(&sm[ZS_OFF + wm * 16 + g + 8 * b], z);
    }
    __syncthreads();

    // ---- output: out = D2 / Z ----
    float rz[2];
    #pragma unroll
    for (int b = 0; b < 2; ++b)
        rz[b] = 1.f / sm[ZS_OFF + wm * 16 + g + 8 * b];

    #pragma unroll
    for (int nt2 = 0; nt2 < 8; ++nt2) {
        #pragma unroll
        for (int b = 0; b < 2; ++b) {
            size_t rowg = (size_t)blockIdx.x * TM + wm * 16 + g + 8 * b;
            int f = wn * 64 + nt2 * 8 + 2 * tig;
            float2 o;
            o.x = d2acc[nt2][2 * b]     * rz[b];
            o.y = d2acc[nt2][2 * b + 1] * rz[b];
            *(float2*)(out + rowg * FDIM + f) = o;
        }
    }
}

extern "C" void kernel_launch(void* const* d_in, const int* in_sizes, int n_in,
                              void* d_out, int out_size) {
    const float* x  = (const float*)d_in[0];
    const float* cc = (const float*)d_in[1];
    if (n_in >= 2 && in_sizes[0] < in_sizes[1]) {   // robustness: x is the big one
        const float* t = x; x = cc; cc = t;
    }

    cudaFuncSetAttribute(cluster_mma_kernel, cudaFuncAttributeMaxDynamicSharedMemorySize,
                         SMEM_BYTES);

    csq_kernel<<<(KCLUST + 255) / 256, 256>>>(cc);
    cluster_mma_kernel<<<MROWS / TM, THREADS, SMEM_BYTES>>>(x, cc, (float*)d_out);
}

// round 17
// speedup vs baseline: 1.0396x; 1.0396x over previous
#include <cuda_runtime.h>
#include <cstdint>
#include <math.h>

// ---------------- problem constants ----------------
#define MROWS   65536        // B*N
#define FDIM    128
#define KCLUST  512
#define TM      128          // rows per CTA
#define TKC     64           // clusters per chunk
#define NCHUNK  (KCLUST / TKC)   // 8
#define THREADS 512

// ---------------- SMEM layout (float offsets) ----------------
// XF : X (tf32-prerounded) in m16n8k8 A-frag order. rows = mt(8)*16+ks(16), pitch 132
// B1H: C chunk tf32, GEMM1 B-frag order (n=cluster,k=feat). rows = nt(8)*16+ks(16), pitch 66
// B2H: C chunk tf32, GEMM2 B-frag order (n=feat,k=cluster). rows = ks2(8)*16+nt2(16), pitch 66
// PF : P chunk (tf32, consistent rounding), GEMM2 A-frag order. rows = mtile(8)*8+ksp(8), pitch 132
#define XF_OFF   0
#define XF_SZ    (128 * 132)
#define B1H_OFF  (XF_OFF + XF_SZ)
#define B1_SZ    (128 * 66)
#define B2H_OFF  (B1H_OFF + B1_SZ)
#define B2_SZ    (128 * 66)
#define PF_OFF   (B2H_OFF + B2_SZ)
#define PF_SZ    (64 * 132)
#define CSQ_OFF  (PF_OFF + PF_SZ)
#define XSQ_OFF  (CSQ_OFF + 512)
#define ZS_OFF   (XSQ_OFF + 128)
#define SMEM_FLOATS (ZS_OFF + 128)
#define SMEM_BYTES  (SMEM_FLOATS * 4)

__device__ float g_csq[KCLUST];

__device__ __forceinline__ uint32_t f2tf32(float x) {
    uint32_t h; asm("cvt.rna.tf32.f32 %0, %1;" : "=r"(h) : "f"(x)); return h;
}

// D(16x8) += A(16x8,tf32) * B(8x8,tf32), fp32 accumulate
__device__ __forceinline__ void mma8(float* d, const uint32_t* a, float2 b) {
    asm volatile(
        "mma.sync.aligned.m16n8k8.row.col.f32.tf32.tf32.f32 "
        "{%0,%1,%2,%3}, {%4,%5,%6,%7}, {%8,%9}, {%0,%1,%2,%3};"
        : "+f"(d[0]), "+f"(d[1]), "+f"(d[2]), "+f"(d[3])
        : "r"(a[0]), "r"(a[1]), "r"(a[2]), "r"(a[3]),
          "r"(__float_as_uint(b.x)), "r"(__float_as_uint(b.y)));
}

__global__ void csq_kernel(const float* __restrict__ cc) {
    int c = blockIdx.x * blockDim.x + threadIdx.x;
    if (c < KCLUST) {
        const float* p = cc + (size_t)c * FDIM;
        float s = 0.f;
        #pragma unroll 16
        for (int f = 0; f < FDIM; ++f) s = fmaf(p[f], p[f], s);
        g_csq[c] = s;
    }
}

extern __shared__ float sm[];

__global__ __launch_bounds__(THREADS, 1)
void cluster_mma_kernel(const float* __restrict__ x, const float* __restrict__ cc,
                        float* __restrict__ out) {
    const int tid  = threadIdx.x;
    const int wid  = tid >> 5;      // 0..15
    const int lane = tid & 31;
    const int g    = lane >> 2;     // groupID (row within m16 tile)
    const int tig  = lane & 3;      // thread-in-group
    const int wm   = wid & 3;       // warp m-group: rows [wm*32, wm*32+32)
    const int wn   = wid >> 2;      // warp n-group: 0..3

    // ------- prologue: pre-rounded tf32 X into A-frag order + exact row sumsq -------
    const float* xbase = x + (size_t)blockIdx.x * TM * FDIM;
    #pragma unroll
    for (int q = 0; q < 8; ++q) {
        int row = q * 16 + wid;                // 0..127
        float4 v = *(const float4*)(xbase + row * FDIM + lane * 4);
        float s = v.x * v.x + v.y * v.y + v.z * v.z + v.w * v.w;
        #pragma unroll
        for (int m = 16; m; m >>= 1) s += __shfl_xor_sync(0xffffffffu, s, m);
        if (lane == 0) sm[XSQ_OFF + row] = s;
        int mt = row >> 4, rm = row & 15;
        int ks = lane >> 1;
        int base = (mt * 16 + ks) * 132 + (rm & 7) * 16 + (rm >> 3) + 2 * (lane & 1);
        #pragma unroll
        for (int j = 0; j < 4; ++j)
            sm[XF_OFF + base + j * 4] = __uint_as_float(f2tf32((&v.x)[j]));
    }
    sm[CSQ_OFF + tid] = g_csq[tid];            // 512 threads cover all 512 entries
    if (tid < 128) sm[ZS_OFF + tid] = 0.f;
    __syncthreads();

    float xs[2][2];
    #pragma unroll
    for (int mt = 0; mt < 2; ++mt)
        #pragma unroll
        for (int b = 0; b < 2; ++b)
            xs[mt][b] = sm[XSQ_OFF + wm * 32 + mt * 16 + g + 8 * b];

    float d2acc[2][4][4];
    #pragma unroll
    for (int mt = 0; mt < 2; ++mt)
        #pragma unroll
        for (int nt = 0; nt < 4; ++nt)
            #pragma unroll
            for (int i = 0; i < 4; ++i) d2acc[mt][nt][i] = 0.f;
    float zacc[2][2] = {{0.f, 0.f}, {0.f, 0.f}};

    // prefetch chunk 0 of C into registers (64 clusters x 128 feats over 512 thr)
    float4 pre[4];
    #pragma unroll
    for (int q = 0; q < 4; ++q) {
        int cl = q * 16 + wid;
        pre[q] = *(const float4*)(cc + (size_t)cl * FDIM + lane * 4);
    }

    for (int kc = 0; kc < NCHUNK; ++kc) {
        __syncthreads();   // previous chunk's B1/B2/PF consumers done

        // ---- stage C chunk from prefetch regs: B1H (k=feat) + B2H (k=cluster) ----
        #pragma unroll
        for (int q = 0; q < 4; ++q) {
            int cl = q * 16 + wid;                     // warp-uniform cluster 0..63
            int nt = cl >> 3;
            int ks = lane >> 1;
            int a1base = (nt * 16 + ks) * 66 + (cl & 7) * 8 + (lane & 1);
            int a2base = (nt * 16 + ks) * 66 + (lane & 1) * 32 + (cl & 3) * 2 + ((cl & 7) >> 2);
            #pragma unroll
            for (int j = 0; j < 4; ++j) {
                float hi = __uint_as_float(f2tf32((&pre[q].x)[j]));
                sm[B1H_OFF + a1base + j * 2] = hi;
                sm[B2H_OFF + a2base + j * 8] = hi;
            }
        }
        __syncthreads();

        // prefetch next chunk (latency hidden behind GEMM1 + epilogue)
        if (kc + 1 < NCHUNK) {
            #pragma unroll
            for (int q = 0; q < 4; ++q) {
                int cl = (kc + 1) * TKC + q * 16 + wid;
                pre[q] = *(const float4*)(cc + (size_t)cl * FDIM + lane * 4);
            }
        }

        // ---- GEMM1: S = x . C^T  (single tf32; operands pre-rounded) ----
        float sacc[2][2][4];
        #pragma unroll
        for (int mt = 0; mt < 2; ++mt)
            #pragma unroll
            for (int nt = 0; nt < 2; ++nt)
                #pragma unroll
                for (int i = 0; i < 4; ++i) sacc[mt][nt][i] = 0.f;

        #pragma unroll
        for (int ks = 0; ks < 16; ++ks) {
            uint32_t a[2][4];
            #pragma unroll
            for (int mt = 0; mt < 2; ++mt) {
                int arow = (wm * 2 + mt) * 16 + ks;
                float4 av = *(const float4*)(sm + XF_OFF + arow * 132 + lane * 4);
                a[mt][0] = __float_as_uint(av.x);
                a[mt][1] = __float_as_uint(av.y);
                a[mt][2] = __float_as_uint(av.z);
                a[mt][3] = __float_as_uint(av.w);
            }
            #pragma unroll
            for (int nt = 0; nt < 2; ++nt) {
                int ntg = wn * 2 + nt;
                float2 bh = *(const float2*)(sm + B1H_OFF + (ntg * 16 + ks) * 66 + lane * 2);
                #pragma unroll
                for (int mt = 0; mt < 2; ++mt)
                    mma8(sacc[mt][nt], a[mt], bh);
            }
        }

        // ---- epilogue: p = exp(-sqrt(xsq+csq-2s)); consistent rna rounding:
        //      Z sums the SAME tf32-rounded p that GEMM2 consumes (no bias) ----
        #pragma unroll
        for (int mt = 0; mt < 2; ++mt) {
            #pragma unroll
            for (int nt = 0; nt < 2; ++nt) {
                int ksp = wn * 2 + nt;
                #pragma unroll
                for (int i = 0; i < 4; ++i) {
                    int b   = i >> 1;                 // row-high
                    int clo = 2 * tig + (i & 1);      // cluster within 8-tile
                    int clg = kc * TKC + ksp * 8 + clo;
                    float s   = sacc[mt][nt][i];
                    float d2v = fmaf(-2.f, s, xs[mt][b] + sm[CSQ_OFF + clg]);
                    float d   = sqrtf(fmaxf(d2v, 0.f));
                    float p   = __expf(-d);
                    float pr  = __uint_as_float(f2tf32(p));   // rna-rounded
                    zacc[mt][b] += pr;
                    sm[PF_OFF + ((wm * 2 + mt) * 8 + ksp) * 132 +
                       (g * 4 + (clo & 3)) * 4 + b + 2 * (clo >> 2)] = pr;
                }
            }
        }
        // PF rows of this wm-group are produced/consumed by its 4 warps (wn 0..3):
        // 128-thread named barrier decouples the four m-groups.
        asm volatile("bar.sync %0, 128;" :: "r"(1 + wm) : "memory");

        // ---- GEMM2: D2 += P . C_chunk  (A pre-rounded, no cvt) ----
        #pragma unroll
        for (int ks2 = 0; ks2 < 8; ++ks2) {
            uint32_t pa[2][4];
            #pragma unroll
            for (int mt = 0; mt < 2; ++mt) {
                float4 pv = *(const float4*)(sm + PF_OFF +
                                ((wm * 2 + mt) * 8 + ks2) * 132 + lane * 4);
                pa[mt][0] = __float_as_uint(pv.x);
                pa[mt][1] = __float_as_uint(pv.y);
                pa[mt][2] = __float_as_uint(pv.z);
                pa[mt][3] = __float_as_uint(pv.w);
            }
            #pragma unroll
            for (int nt2 = 0; nt2 < 4; ++nt2) {
                int n2g = wn * 4 + nt2;
                float2 b = *(const float2*)(sm + B2H_OFF + (ks2 * 16 + n2g) * 66 + lane * 2);
                #pragma unroll
                for (int mt = 0; mt < 2; ++mt)
                    mma8(d2acc[mt][nt2], pa[mt], b);
            }
        }
    }

    // ---- Z reduction across tig lanes + the four wn warp-groups ----
    #pragma unroll
    for (int mt = 0; mt < 2; ++mt)
        #pragma unroll
        for (int b = 0; b < 2; ++b) {
            float z = zacc[mt][b];
            z += __shfl_xor_sync(0xffffffffu, z, 1);
            z += __shfl_xor_sync(0xffffffffu, z, 2);
            if (tig == 0)
                atomicAdd(&sm[ZS_OFF + wm * 32 + mt * 16 + g + 8 * b], z);
        }
    __syncthreads();

    // ---- output: out = D2 / Z ----
    float rz[2][2];
    #pragma unroll
    for (int mt = 0; mt < 2; ++mt)
        #pragma unroll
        for (int b = 0; b < 2; ++b)
            rz[mt][b] = 1.f / sm[ZS_OFF + wm * 32 + mt * 16 + g + 8 * b];

    #pragma unroll
    for (int mt = 0; mt < 2; ++mt) {
        #pragma unroll
        for (int nt2 = 0; nt2 < 4; ++nt2) {
            #pragma unroll
            for (int b = 0; b < 2; ++b) {
                size_t rowg = (size_t)blockIdx.x * TM + wm * 32 + mt * 16 + g + 8 * b;
                int f = wn * 32 + nt2 * 8 + 2 * tig;
                float2 o;
                o.x = d2acc[mt][nt2][2 * b]     * rz[mt][b];
                o.y = d2acc[mt][nt2][2 * b + 1] * rz[mt][b];
                *(float2*)(out + rowg * FDIM + f) = o;
            }
        }
    }
}

extern "C" void kernel_launch(void* const* d_in, const int* in_sizes, int n_in,
                              void* d_out, int out_size) {
    const float* x  = (const float*)d_in[0];
    const float* cc = (const float*)d_in[1];
    if (n_in >= 2 && in_sizes[0] < in_sizes[1]) {   // robustness: x is the big one
        const float* t = x; x = cc; cc = t;
    }

    cudaFuncSetAttribute(cluster_mma_kernel, cudaFuncAttributeMaxDynamicSharedMemorySize,
                         SMEM_BYTES);

    csq_kernel<<<(KCLUST + 255) / 256, 256>>>(cc);
    cluster_mma_kernel<<<MROWS / TM, THREADS, SMEM_BYTES>>>(x, cc, (float*)d_out);
}